// round 16
// baseline (speedup 1.0000x reference)
#include <cuda_runtime.h>
#include <cuda_fp16.h>
#include <math.h>
#include <stdint.h>

// Problem constants
#define BB   4
#define TT   2048
#define DD   1024
#define HH   16
#define HD   64
#define BT   (BB * TT)        // 8192
#define D3   (3 * DD)         // 3072

// Scratch (allocation-free rule: __device__ globals)
__device__ __half g_qh[BT * D3];     // qkv hi [8192][3072]
__device__ __half g_ql[BT * D3];     // qkv lo
__device__ __half g_ah[BT * DD];     // activation hi (x-split, then attn out)
__device__ __half g_al[BT * DD];     // activation lo
__device__ __half g_bh[DD * D3];     // weight^T hi
__device__ __half g_bl[DD * D3];     // weight^T lo

__device__ __forceinline__ uint32_t smem_u32(const void* p) {
    uint32_t a;
    asm("{ .reg .u64 t; cvta.to.shared.u64 t, %1; cvt.u32.u64 %0, t; }" : "=r"(a) : "l"(p));
    return a;
}

#define CP_ASYNC16(saddr, gptr) \
    asm volatile("cp.async.cg.shared.global [%0], [%1], 16;" :: "r"(saddr), "l"(gptr) : "memory")
#define CP_COMMIT() asm volatile("cp.async.commit_group;" ::: "memory")
#define CP_WAIT1()  asm volatile("cp.async.wait_group 1;" ::: "memory")
#define CP_WAIT0()  asm volatile("cp.async.wait_group 0;" ::: "memory")

__device__ __forceinline__ void mma16816(float* c, const uint32_t* a, const uint32_t* b) {
    asm volatile(
        "mma.sync.aligned.m16n8k16.row.col.f32.f16.f16.f32 "
        "{%0,%1,%2,%3}, {%4,%5,%6,%7}, {%8,%9}, {%0,%1,%2,%3};"
        : "+f"(c[0]), "+f"(c[1]), "+f"(c[2]), "+f"(c[3])
        : "r"(a[0]), "r"(a[1]), "r"(a[2]), "r"(a[3]), "r"(b[0]), "r"(b[1]));
}

__device__ __forceinline__ void ldsm_x4(uint32_t* r, uint32_t addr) {
    asm volatile("ldmatrix.sync.aligned.m8n8.x4.shared.b16 {%0,%1,%2,%3}, [%4];"
                 : "=r"(r[0]), "=r"(r[1]), "=r"(r[2]), "=r"(r[3]) : "r"(addr));
}
__device__ __forceinline__ void ldsm_x4_t(uint32_t* r, uint32_t addr) {
    asm volatile("ldmatrix.sync.aligned.m8n8.x4.trans.shared.b16 {%0,%1,%2,%3}, [%4];"
                 : "=r"(r[0]), "=r"(r[1]), "=r"(r[2]), "=r"(r[3]) : "r"(addr));
}

__device__ __forceinline__ void split2(float a, float b, uint32_t& h, uint32_t& l) {
    __half ha = __float2half_rn(a), hb = __float2half_rn(b);
    __half la = __float2half_rn(a - __half2float(ha));
    __half lb = __float2half_rn(b - __half2float(hb));
    __half2 H(ha, hb), L(la, lb);
    h = *(uint32_t*)&H; l = *(uint32_t*)&L;
}
__device__ __forceinline__ uint32_t pack2(float a, float b) {
    __half2 t = __floats2half2_rn(a, b);   // low = a, high = b
    return *(uint32_t*)&t;
}

// ---------------------------------------------------------------------------
// fp32 -> (hi, lo) fp16 split, elementwise.
// ---------------------------------------------------------------------------
__global__ __launch_bounds__(256)
void split_kernel(const float* __restrict__ in, __half* __restrict__ hi,
                  __half* __restrict__ lo, int n) {
    int i = (blockIdx.x * 256 + threadIdx.x) * 4;
    if (i >= n) return;
    float4 v = *(const float4*)(in + i);
    uint32_t h0, l0, h1, l1;
    split2(v.x, v.y, h0, l0);
    split2(v.z, v.w, h1, l1);
    uint32_t* hp = (uint32_t*)(hi + i);
    uint32_t* lp = (uint32_t*)(lo + i);
    hp[0] = h0; hp[1] = h1; lp[0] = l0; lp[1] = l1;
}

// ---------------------------------------------------------------------------
// W [K,N] fp32 row-major -> Wt hi/lo [N,K] fp16 row-major (transpose + split)
// ---------------------------------------------------------------------------
__global__ __launch_bounds__(256)
void transpose_split(const float* __restrict__ W, __half* __restrict__ Th,
                     __half* __restrict__ Tl, int K, int N) {
    __shared__ float t[32][33];
    const int k0 = blockIdx.y * 32, n0 = blockIdx.x * 32;
    const int tx = threadIdx.x & 31, ty = threadIdx.x >> 5;
    #pragma unroll
    for (int i = 0; i < 32; i += 8)
        t[ty + i][tx] = W[(size_t)(k0 + ty + i) * N + n0 + tx];
    __syncthreads();
    #pragma unroll
    for (int i = 0; i < 32; i += 8) {
        float v = t[tx][ty + i];
        __half h = __float2half_rn(v);
        size_t o = (size_t)(n0 + ty + i) * K + k0 + tx;
        Th[o] = h;
        Tl[o] = __float2half_rn(v - __half2float(h));
    }
}

// ---------------------------------------------------------------------------
// mma.sync fp16 split-GEMM (3-term), ldmatrix fragments, term-major MMA
// passes so any two MMAs hitting the same accumulator are >=16 apart.
// ---------------------------------------------------------------------------
#define TS   (128 * 40)
#define STG  (4 * TS)

template <bool SPLIT_OUT>
__global__ __launch_bounds__(256)
void gemm_mma(const __half* __restrict__ Ah, const __half* __restrict__ Al,
              const __half* __restrict__ Bh, const __half* __restrict__ Bl,
              float* __restrict__ C, __half* __restrict__ Ch,
              __half* __restrict__ Cl, int N, int K) {
    extern __shared__ __align__(16) __half sm[];
    const uint32_t sb = smem_u32(sm);

    const int tid  = threadIdx.x;
    const int wid  = tid >> 5;
    const int lane = tid & 31;
    const int g    = lane >> 2;
    const int tg   = lane & 3;
    const int wm   = (wid >> 1) * 32;
    const int wn   = (wid & 1) * 64;
    const int m0   = blockIdx.y * 128;
    const int n0   = blockIdx.x * 128;

    const int arow_l = ((lane >> 3) & 1) * 8 + (lane & 7);
    const int acol_l = (lane >> 4) * 8;
    const int brow_l = ((lane >> 4) & 1) * 8 + (lane & 7);
    const int bcol_l = ((lane >> 3) & 1) * 8;

    float acc[2][8][4];
    #pragma unroll
    for (int i = 0; i < 2; i++)
        #pragma unroll
        for (int j = 0; j < 8; j++)
            #pragma unroll
            for (int c = 0; c < 4; c++) acc[i][j][c] = 0.0f;

    const int KT = K >> 5;

    auto issue = [&](int stage, int kt) {
        const int k0 = kt * 32;
        uint32_t sbase = sb + stage * STG * 2;
        #pragma unroll
        for (int h = 0; h < 2; h++) {
            int c   = tid + h * 256;
            int row = c >> 2;
            int cc  = c & 3;
            size_t ga = (size_t)(m0 + row) * K + k0 + cc * 8;
            size_t gb = (size_t)(n0 + row) * K + k0 + cc * 8;
            uint32_t so = (uint32_t)(row * 80 + cc * 16);
            CP_ASYNC16(sbase + so,          Ah + ga);
            CP_ASYNC16(sbase + TS * 2 + so, Al + ga);
            CP_ASYNC16(sbase + TS * 4 + so, Bh + gb);
            CP_ASYNC16(sbase + TS * 6 + so, Bl + gb);
        }
        CP_COMMIT();
    };

    issue(0, 0);

    for (int kt = 0; kt < KT; kt++) {
        const int stage = kt & 1;
        if (kt + 1 < KT) { issue(stage ^ 1, kt + 1); CP_WAIT1(); }
        else             { CP_WAIT0(); }
        __syncthreads();

        const uint32_t sAh = sb + stage * STG * 2;
        const uint32_t sAl = sAh + TS * 2;
        const uint32_t sBh = sAh + TS * 4;
        const uint32_t sBl = sAh + TS * 6;

        #pragma unroll
        for (int ks = 0; ks < 32; ks += 16) {
            uint32_t ah[2][4], al[2][4], bh[4][4], bl[4][4];
            #pragma unroll
            for (int i = 0; i < 2; i++) {
                uint32_t off = (uint32_t)((wm + i * 16 + arow_l) * 40 + ks + acol_l) * 2;
                ldsm_x4(ah[i], sAh + off);
                ldsm_x4(al[i], sAl + off);
            }
            #pragma unroll
            for (int jp = 0; jp < 4; jp++) {
                uint32_t off = (uint32_t)((wn + jp * 16 + brow_l) * 40 + ks + bcol_l) * 2;
                ldsm_x4(bh[jp], sBh + off);
                ldsm_x4(bl[jp], sBl + off);
            }
            // pass 1: Ah*Bh  (16 independent accumulators)
            #pragma unroll
            for (int i = 0; i < 2; i++)
                #pragma unroll
                for (int jp = 0; jp < 4; jp++) {
                    mma16816(acc[i][2 * jp],     ah[i], &bh[jp][0]);
                    mma16816(acc[i][2 * jp + 1], ah[i], &bh[jp][2]);
                }
            // pass 2: Ah*Bl
            #pragma unroll
            for (int i = 0; i < 2; i++)
                #pragma unroll
                for (int jp = 0; jp < 4; jp++) {
                    mma16816(acc[i][2 * jp],     ah[i], &bl[jp][0]);
                    mma16816(acc[i][2 * jp + 1], ah[i], &bl[jp][2]);
                }
            // pass 3: Al*Bh
            #pragma unroll
            for (int i = 0; i < 2; i++)
                #pragma unroll
                for (int jp = 0; jp < 4; jp++) {
                    mma16816(acc[i][2 * jp],     al[i], &bh[jp][0]);
                    mma16816(acc[i][2 * jp + 1], al[i], &bh[jp][2]);
                }
        }
        __syncthreads();
    }

    #pragma unroll
    for (int i = 0; i < 2; i++) {
        int r0 = m0 + wm + i * 16 + g;
        #pragma unroll
        for (int j = 0; j < 8; j++) {
            int cc = n0 + wn + j * 8 + tg * 2;
            if constexpr (SPLIT_OUT) {
                uint32_t h01, l01, h23, l23;
                split2(acc[i][j][0], acc[i][j][1], h01, l01);
                split2(acc[i][j][2], acc[i][j][3], h23, l23);
                *(uint32_t*)(Ch + (size_t)r0 * N + cc)       = h01;
                *(uint32_t*)(Cl + (size_t)r0 * N + cc)       = l01;
                *(uint32_t*)(Ch + (size_t)(r0 + 8) * N + cc) = h23;
                *(uint32_t*)(Cl + (size_t)(r0 + 8) * N + cc) = l23;
            } else {
                *(float2*)(C + (size_t)r0 * N + cc)       = make_float2(acc[i][j][0], acc[i][j][1]);
                *(float2*)(C + (size_t)(r0 + 8) * N + cc) = make_float2(acc[i][j][2], acc[i][j][3]);
            }
        }
    }
}

// ---------------------------------------------------------------------------
// Flash attention, fp16 mma + ldmatrix, half-tile softmax/MMA overlap,
// term-major MMA passes (dependent accumulator reuse >= 8 MMAs apart).
// S: 3-term split.  PV: P single fp16, V hi/lo -> 2 terms.
// smem: Qh 0 | Ql 18432 | stage s at 36864+s*73728: Kh|Kl|Vh|Vl (18432 each).
// ---------------------------------------------------------------------------
#define ASTR 72
#define SM_ST0 36864
#define STAGE_B 73728
#define ATTN_SMEM 184320

__global__ __launch_bounds__(256, 1)
void attn_mma(const __half* __restrict__ qh, const __half* __restrict__ ql,
              __half* __restrict__ oh, __half* __restrict__ ol) {
    extern __shared__ __align__(16) char smc[];
    const uint32_t sb = smem_u32(smc);

    const int tid  = threadIdx.x;
    const int wid  = tid >> 5;
    const int lane = tid & 31;
    const int g    = lane >> 2;
    const int tg   = lane & 3;
    const int wq   = wid * 16;
    const int qb   = blockIdx.x;
    const int h    = blockIdx.y;
    const int b    = blockIdx.z;
    const int t0   = qb * 128;

    const int lrow  = tid >> 1;
    const int cbase = (tid & 1) * 32;

    const int arow_l = ((lane >> 3) & 1) * 8 + (lane & 7);
    const int acol_l = (lane >> 4) * 8;
    const int brow_l = ((lane >> 4) & 1) * 8 + (lane & 7);
    const int bcol_l = ((lane >> 3) & 1) * 8;
    const int vrow_l = ((lane >> 3) & 1) * 8 + (lane & 7);
    const int vcol_l = ((lane >> 4) & 1) * 8;

    // Prologue: Q + K(0) + V(0) via cp.async
    {
        const size_t qgrow = ((size_t)(b * TT + t0) + lrow) * D3 + h * HD + cbase;
        const size_t base0 = ((size_t)(b * TT) + lrow) * D3 + h * HD + cbase;
        #pragma unroll
        for (int i = 0; i < 4; i++) {
            uint32_t so = (uint32_t)(lrow * (ASTR * 2) + (cbase + i * 8) * 2);
            CP_ASYNC16(sb + so,         qh + qgrow + i * 8);
            CP_ASYNC16(sb + 18432 + so, ql + qgrow + i * 8);
            CP_ASYNC16(sb + SM_ST0 + so,         qh + base0 + DD + i * 8);
            CP_ASYNC16(sb + SM_ST0 + 18432 + so, ql + base0 + DD + i * 8);
            CP_ASYNC16(sb + SM_ST0 + 36864 + so, qh + base0 + 2 * DD + i * 8);
            CP_ASYNC16(sb + SM_ST0 + 55296 + so, ql + base0 + 2 * DD + i * 8);
        }
        CP_COMMIT();
    }
    CP_WAIT0();
    __syncthreads();

    // Q fragments (persistent)
    uint32_t aQh[4][4], aQl[4][4];
    #pragma unroll
    for (int ks = 0; ks < 4; ks++) {
        uint32_t off = (uint32_t)((wq + arow_l) * ASTR + ks * 16 + acol_l) * 2;
        ldsm_x4(aQh[ks], sb + off);
        ldsm_x4(aQl[ks], sb + 18432 + off);
    }

    float O[8][4];
    #pragma unroll
    for (int j = 0; j < 8; j++)
        #pragma unroll
        for (int c = 0; c < 4; c++) O[j][c] = 0.0f;
    float m0v = -1e30f, m1v = -1e30f, l0v = 0.0f, l1v = 0.0f;

    const int NT = TT / 128;
    for (int kv = 0; kv < NT; kv++) {
        const int stage = kv & 1;
        if (kv > 0) { CP_WAIT0(); __syncthreads(); }

        if (kv + 1 < NT) {
            const size_t base = ((size_t)(b * TT + (kv + 1) * 128) + lrow) * D3 + h * HD + cbase;
            uint32_t dst = sb + SM_ST0 + (stage ^ 1) * STAGE_B;
            #pragma unroll
            for (int i = 0; i < 4; i++) {
                uint32_t so = (uint32_t)(lrow * (ASTR * 2) + (cbase + i * 8) * 2);
                CP_ASYNC16(dst + so,         qh + base + DD + i * 8);
                CP_ASYNC16(dst + 18432 + so, ql + base + DD + i * 8);
                CP_ASYNC16(dst + 36864 + so, qh + base + 2 * DD + i * 8);
                CP_ASYNC16(dst + 55296 + so, ql + base + 2 * DD + i * 8);
            }
            CP_COMMIT();
        }

        const uint32_t sK = sb + SM_ST0 + stage * STAGE_B;
        const uint32_t sV = sK + 36864;

        float c[16][4];
        #pragma unroll
        for (int j = 0; j < 16; j++)
            #pragma unroll
            for (int x = 0; x < 4; x++) c[j][x] = 0.0f;

        // ---- S-MMA, term-major passes: 8 independent accs per pass ----
        #pragma unroll
        for (int half = 0; half < 2; half++) {
            #pragma unroll
            for (int ks = 0; ks < 4; ks++) {
                uint32_t kh[4][4], kl[4][4];
                #pragma unroll
                for (int q = 0; q < 4; q++) {
                    int jp = 4 * half + q;
                    uint32_t off = (uint32_t)((jp * 16 + brow_l) * ASTR + ks * 16 + bcol_l) * 2;
                    ldsm_x4(kh[q], sK + off);
                    ldsm_x4(kl[q], sK + 18432 + off);
                }
                // pass hh
                #pragma unroll
                for (int q = 0; q < 4; q++) {
                    int jp = 4 * half + q;
                    mma16816(c[2 * jp],     aQh[ks], &kh[q][0]);
                    mma16816(c[2 * jp + 1], aQh[ks], &kh[q][2]);
                }
                // pass hl
                #pragma unroll
                for (int q = 0; q < 4; q++) {
                    int jp = 4 * half + q;
                    mma16816(c[2 * jp],     aQh[ks], &kl[q][0]);
                    mma16816(c[2 * jp + 1], aQh[ks], &kl[q][2]);
                }
                // pass lh
                #pragma unroll
                for (int q = 0; q < 4; q++) {
                    int jp = 4 * half + q;
                    mma16816(c[2 * jp],     aQl[ks], &kh[q][0]);
                    mma16816(c[2 * jp + 1], aQl[ks], &kh[q][2]);
                }
            }
        }

        // ---- interleaved: softmax(half) then PV(half) ----
        #pragma unroll
        for (int half = 0; half < 2; half++) {
            const int jb = 8 * half;
            float mx0 = c[jb][0], mx1 = c[jb][2];
            #pragma unroll
            for (int j = jb; j < jb + 8; j++) {
                mx0 = fmaxf(mx0, fmaxf(c[j][0], c[j][1]));
                mx1 = fmaxf(mx1, fmaxf(c[j][2], c[j][3]));
            }
            mx0 = fmaxf(mx0, __shfl_xor_sync(0xffffffffu, mx0, 1));
            mx0 = fmaxf(mx0, __shfl_xor_sync(0xffffffffu, mx0, 2));
            mx1 = fmaxf(mx1, __shfl_xor_sync(0xffffffffu, mx1, 1));
            mx1 = fmaxf(mx1, __shfl_xor_sync(0xffffffffu, mx1, 2));

            float mn0 = fmaxf(m0v, mx0), mn1 = fmaxf(m1v, mx1);
            float sc0 = __expf(m0v - mn0), sc1 = __expf(m1v - mn1);
            float sum0 = 0.0f, sum1 = 0.0f;
            #pragma unroll
            for (int j = jb; j < jb + 8; j++) {
                c[j][0] = __expf(c[j][0] - mn0); sum0 += c[j][0];
                c[j][1] = __expf(c[j][1] - mn0); sum0 += c[j][1];
                c[j][2] = __expf(c[j][2] - mn1); sum1 += c[j][2];
                c[j][3] = __expf(c[j][3] - mn1); sum1 += c[j][3];
            }
            sum0 += __shfl_xor_sync(0xffffffffu, sum0, 1);
            sum0 += __shfl_xor_sync(0xffffffffu, sum0, 2);
            sum1 += __shfl_xor_sync(0xffffffffu, sum1, 1);
            sum1 += __shfl_xor_sync(0xffffffffu, sum1, 2);
            l0v = l0v * sc0 + sum0;  m0v = mn0;
            l1v = l1v * sc1 + sum1;  m1v = mn1;
            #pragma unroll
            for (int j = 0; j < 8; j++) {
                O[j][0] *= sc0; O[j][1] *= sc0; O[j][2] *= sc1; O[j][3] *= sc1;
            }

            // PV: term-major (vh pass x8, vl pass x8)
            #pragma unroll
            for (int kk = 4 * half; kk < 4 * half + 4; kk++) {
                uint32_t p[4];
                p[0] = pack2(c[2 * kk][0],     c[2 * kk][1]);
                p[1] = pack2(c[2 * kk][2],     c[2 * kk][3]);
                p[2] = pack2(c[2 * kk + 1][0], c[2 * kk + 1][1]);
                p[3] = pack2(c[2 * kk + 1][2], c[2 * kk + 1][3]);
                uint32_t vh[4][4], vl[4][4];
                #pragma unroll
                for (int jnp = 0; jnp < 4; jnp++) {
                    uint32_t off = (uint32_t)((kk * 16 + vrow_l) * ASTR + jnp * 16 + vcol_l) * 2;
                    ldsm_x4_t(vh[jnp], sV + off);
                    ldsm_x4_t(vl[jnp], sV + 18432 + off);
                }
                #pragma unroll
                for (int jnp = 0; jnp < 4; jnp++) {
                    mma16816(O[2 * jnp],     p, &vh[jnp][0]);
                    mma16816(O[2 * jnp + 1], p, &vh[jnp][2]);
                }
                #pragma unroll
                for (int jnp = 0; jnp < 4; jnp++) {
                    mma16816(O[2 * jnp],     p, &vl[jnp][0]);
                    mma16816(O[2 * jnp + 1], p, &vl[jnp][2]);
                }
            }
        }
    }

    // Epilogue: normalize, split, write fp16 hi/lo into proj-A buffers
    float inv0 = 1.0f / l0v, inv1 = 1.0f / l1v;
    size_t r0 = (size_t)(b * TT + t0 + wq + g);
    size_t col = h * HD + tg * 2;
    #pragma unroll
    for (int jn = 0; jn < 8; jn++) {
        uint32_t h01, l01, h23, l23;
        split2(O[jn][0] * inv0, O[jn][1] * inv0, h01, l01);
        split2(O[jn][2] * inv1, O[jn][3] * inv1, h23, l23);
        size_t o0 = r0 * DD + col + jn * 8;
        size_t o1 = (r0 + 8) * DD + col + jn * 8;
        *(uint32_t*)(oh + o0) = h01;
        *(uint32_t*)(ol + o0) = l01;
        *(uint32_t*)(oh + o1) = h23;
        *(uint32_t*)(ol + o1) = l23;
    }
}

// ---------------------------------------------------------------------------
// kernel_launch
// ---------------------------------------------------------------------------
extern "C" void kernel_launch(void* const* d_in, const int* in_sizes, int n_in,
                              void* d_out, int out_size) {
    const float* x      = (const float*)d_in[0];
    const float* w_qkv  = (const float*)d_in[1];
    const float* w_proj = (const float*)d_in[2];
    float* out = (float*)d_out;

    __half *qh, *ql, *ah, *al, *bh, *bl;
    cudaGetSymbolAddress((void**)&qh, g_qh);
    cudaGetSymbolAddress((void**)&ql, g_ql);
    cudaGetSymbolAddress((void**)&ah, g_ah);
    cudaGetSymbolAddress((void**)&al, g_al);
    cudaGetSymbolAddress((void**)&bh, g_bh);
    cudaGetSymbolAddress((void**)&bl, g_bl);

    const int gemm_smem = 2 * STG * 2;
    cudaFuncSetAttribute(gemm_mma<true>,  cudaFuncAttributeMaxDynamicSharedMemorySize, gemm_smem);
    cudaFuncSetAttribute(gemm_mma<false>, cudaFuncAttributeMaxDynamicSharedMemorySize, gemm_smem);
    cudaFuncSetAttribute(attn_mma, cudaFuncAttributeMaxDynamicSharedMemorySize, ATTN_SMEM);

    const int n_act = BT * DD;

    split_kernel<<<n_act / 1024, 256>>>(x, ah, al, n_act);
    transpose_split<<<dim3(D3 / 32, DD / 32), 256>>>(w_qkv, bh, bl, DD, D3);
    gemm_mma<true><<<dim3(D3 / 128, BT / 128), 256, gemm_smem>>>(
        ah, al, bh, bl, nullptr, qh, ql, D3, DD);
    attn_mma<<<dim3(TT / 128, HH, BB), 256, ATTN_SMEM>>>(qh, ql, ah, al);
    transpose_split<<<dim3(DD / 32, DD / 32), 256>>>(w_proj, bh, bl, DD, DD);
    gemm_mma<false><<<dim3(DD / 128, BT / 128), 256, gemm_smem>>>(
        ah, al, bh, bl, out, nullptr, nullptr, DD, DD);
}